// round 5
// baseline (speedup 1.0000x reference)
#include <cuda_runtime.h>

// PS-ROI-Align, fixed dims:
//   input: (N=4, C=490, H=100, W=100) f32
//   rois:  (K=2048, 5) f32  [batch, x1, y1, x2, y2]
//   out:   (K, 10, 7, 7) f32,  POOL=7, SCALE=1/16, GRID=2
//
// One thread per output element. All 8 float4 loads (4 rows x 2 halves)
// issued as one front batch for MLP=8; inactive rows are duplicated to an
// active row (weight 0) so the extra lanes hit already-touched lines (no
// added L1 wavefronts). Second half per row is flat-predicated.

#define C_TOT   490
#define HH      100
#define WW      100
#define POOL    7
#define SSCALE  0.0625f

__global__ __launch_bounds__(256) void psroi_align_kernel(
    const float* __restrict__ input,
    const float* __restrict__ rois,
    float* __restrict__ out)
{
    int k = blockIdx.x >> 1;
    int r = ((blockIdx.x & 1) << 8) + threadIdx.x;   // 0..511
    if (r >= C_TOT) return;

    int pw = r % POOL;
    int ph = (r / POOL) % POOL;

    const float* roi = rois + k * 5;
    int   b  = (int)__ldg(roi + 0);
    float x1 = __ldg(roi + 1) * SSCALE - 0.5f;
    float y1 = __ldg(roi + 2) * SSCALE - 0.5f;
    float x2 = __ldg(roi + 3) * SSCALE - 0.5f;
    float y2 = __ldg(roi + 4) * SSCALE - 0.5f;

    float bsh = (y2 - y1) * (1.0f / POOL);
    float bsw = (x2 - x1) * (1.0f / POOL);

    const float* base = input + ((long)b * C_TOT + r) * (HH * WW);

    // ---- x taps (samples at +0.25, +0.75 of bin) ----
    float tx0 = fmaxf(x1 + ((float)pw + 0.25f) * bsw, 0.0f);
    float tx1 = fmaxf(x1 + ((float)pw + 0.75f) * bsw, 0.0f);
    int xl0 = min((int)tx0, WW - 1);
    int xl1 = min((int)tx1, WW - 1);
    int xh0 = min(xl0 + 1, WW - 1);
    int xh1 = min(xl1 + 1, WW - 1);
    float fx0 = (xl0 >= WW - 1) ? 0.0f : tx0 - (float)xl0;
    float fx1 = (xl1 >= WW - 1) ? 0.0f : tx1 - (float)xl1;

    // ---- y taps ----
    float ty0 = fmaxf(y1 + ((float)ph + 0.25f) * bsh, 0.0f);
    float ty1 = fmaxf(y1 + ((float)ph + 0.75f) * bsh, 0.0f);
    int yl0 = min((int)ty0, HH - 1);
    int yl1 = min((int)ty1, HH - 1);
    int yh0 = min(yl0 + 1, HH - 1);
    int yh1 = min(yl1 + 1, HH - 1);
    float fy0 = (yl0 >= HH - 1) ? 0.0f : ty0 - (float)yl0;
    float fy1 = (yl1 >= HH - 1) ? 0.0f : ty1 - (float)yl1;

    float a0 = 1.0f - fy0, a1 = fy0;
    float a2 = 1.0f - fy1, a3 = fy1;

    // ---- branch-free row dedup: 4 row slots, inactive -> dup row 0, w=0 ----
    bool same_pair = (yl1 == yl0);            // rows {2,3} duplicate {0,1}
    bool shift_one = (yl1 == yh0);            // row2 == row1
    bool act2 = !same_pair;
    bool act3 = !same_pair && !shift_one;

    int   ry0 = yl0;
    int   ry1 = yh0;
    int   ry2 = act2 ? (shift_one ? yh1 : yl1) : yl0;
    int   ry3 = act3 ? yh1 : yl0;
    float wr0 = a0 + (same_pair ? a2 : 0.0f);
    float wr1 = a1 + (same_pair ? a3 : (shift_one ? a2 : 0.0f));
    float wr2 = act2 ? (shift_one ? a3 : a2) : 0.0f;
    float wr3 = act3 ? a3 : 0.0f;

    // ---- aligned x window ----
    int wbase = xl0 & ~3;                     // 16B aligned, f0 in-bounds
    int o_l0 = xl0 - wbase, o_h0 = xh0 - wbase;
    int o_l1 = xl1 - wbase, o_h1 = xh1 - wbase;

    float acc;

    if (o_h1 <= 7) {
        float w[8];
        #pragma unroll
        for (int j = 0; j < 8; ++j) {
            float v = (j == o_l0) ? (1.0f - fx0) : 0.0f;
            v += (j == o_h0) ? fx0 : 0.0f;
            v += (j == o_l1) ? (1.0f - fx1) : 0.0f;
            v += (j == o_h1) ? fx1 : 0.0f;
            w[j] = v;
        }
        bool need2 = (o_h1 > 3);
        const float* rowbase = base + wbase;
        const float4* p0 = (const float4*)(rowbase + ry0 * WW);
        const float4* p1 = (const float4*)(rowbase + ry1 * WW);
        const float4* p2 = (const float4*)(rowbase + ry2 * WW);
        const float4* p3 = (const float4*)(rowbase + ry3 * WW);

        // front-batched loads: 4 unconditional + 4 flat-predicated
        float4 A0 = __ldg(p0);
        float4 A1 = __ldg(p1);
        float4 A2 = __ldg(p2);
        float4 A3 = __ldg(p3);
        float4 Z  = make_float4(0.f, 0.f, 0.f, 0.f);
        float4 B0 = need2 ? __ldg(p0 + 1) : Z;
        float4 B1 = need2 ? __ldg(p1 + 1) : Z;
        float4 B2 = need2 ? __ldg(p2 + 1) : Z;
        float4 B3 = need2 ? __ldg(p3 + 1) : Z;

        float s0 = A0.x * w[0] + A0.y * w[1] + A0.z * w[2] + A0.w * w[3]
                 + B0.x * w[4] + B0.y * w[5] + B0.z * w[6] + B0.w * w[7];
        float s1 = A1.x * w[0] + A1.y * w[1] + A1.z * w[2] + A1.w * w[3]
                 + B1.x * w[4] + B1.y * w[5] + B1.z * w[6] + B1.w * w[7];
        float s2 = A2.x * w[0] + A2.y * w[1] + A2.z * w[2] + A2.w * w[3]
                 + B2.x * w[4] + B2.y * w[5] + B2.z * w[6] + B2.w * w[7];
        float s3 = A3.x * w[0] + A3.y * w[1] + A3.z * w[2] + A3.w * w[3]
                 + B3.x * w[4] + B3.y * w[5] + B3.z * w[6] + B3.w * w[7];

        acc = wr0 * s0 + wr1 * s1 + wr2 * s2 + wr3 * s3;
    } else {
        // rare wide-roi fallback: scalar taps (still front-batched per row)
        float wx0 = 1.0f - fx0, wx1 = fx0, wx2 = 1.0f - fx1, wx3 = fx1;
        const float* q0 = base + ry0 * WW;
        const float* q1 = base + ry1 * WW;
        const float* q2 = base + ry2 * WW;
        const float* q3 = base + ry3 * WW;
        float s0 = wx0 * __ldg(q0 + xl0) + wx1 * __ldg(q0 + xh0)
                 + wx2 * __ldg(q0 + xl1) + wx3 * __ldg(q0 + xh1);
        float s1 = wx0 * __ldg(q1 + xl0) + wx1 * __ldg(q1 + xh0)
                 + wx2 * __ldg(q1 + xl1) + wx3 * __ldg(q1 + xh1);
        float s2 = wx0 * __ldg(q2 + xl0) + wx1 * __ldg(q2 + xh0)
                 + wx2 * __ldg(q2 + xl1) + wx3 * __ldg(q2 + xh1);
        float s3 = wx0 * __ldg(q3 + xl0) + wx1 * __ldg(q3 + xh0)
                 + wx2 * __ldg(q3 + xl1) + wx3 * __ldg(q3 + xh1);
        acc = wr0 * s0 + wr1 * s1 + wr2 * s2 + wr3 * s3;
    }

    out[k * C_TOT + r] = acc * 0.25f;
}

extern "C" void kernel_launch(void* const* d_in, const int* in_sizes, int n_in,
                              void* d_out, int out_size)
{
    const float* input = (const float*)d_in[0];
    const float* rois  = (const float*)d_in[1];
    float* out = (float*)d_out;

    psroi_align_kernel<<<2048 * 2, 256>>>(input, rois, out);
}

// round 6
// speedup vs baseline: 1.0077x; 1.0077x over previous
#include <cuda_runtime.h>

// PS-ROI-Align, fixed dims:
//   input: (N=4, C=490, H=100, W=100) f32
//   rois:  (K=2048, 5) f32  [batch, x1, y1, x2, y2]
//   out:   (K, 10, 7, 7) f32,  POOL=7, SCALE=1/16, GRID=2
//
// One block per roi (roi math shared/broadcast), 2 output elements per
// thread (r = t and t+256) -> 2 independent load pipelines per thread for
// double memory-level parallelism at an unchanged L1-wavefront count.
// Per element: R4's predicated load set (rows 0,1 always; rows 2,3
// act-predicated; 2nd float4 per row need2-predicated), reduction via
// vector row accumulators then a single dot with the x-weight vector.

#define C_TOT   490
#define HH      100
#define WW      100
#define POOL    7
#define SSCALE  0.0625f
#define PLANE   (HH * WW)

__device__ __forceinline__ float compute_elem(
    const float* __restrict__ baseimg,   // input + b*C_TOT*PLANE
    int r, float x1, float y1, float bsw, float bsh)
{
    int pw = r % POOL;
    int ph = (r / POOL) % POOL;

    const float* base = baseimg + r * PLANE;

    // ---- x taps (samples at +0.25, +0.75 of bin) ----
    float tx0 = fmaxf(x1 + ((float)pw + 0.25f) * bsw, 0.0f);
    float tx1 = fmaxf(x1 + ((float)pw + 0.75f) * bsw, 0.0f);
    int xl0 = min((int)tx0, WW - 1);
    int xl1 = min((int)tx1, WW - 1);
    int xh0 = min(xl0 + 1, WW - 1);
    int xh1 = min(xl1 + 1, WW - 1);
    float fx0 = (xl0 >= WW - 1) ? 0.0f : tx0 - (float)xl0;
    float fx1 = (xl1 >= WW - 1) ? 0.0f : tx1 - (float)xl1;

    // ---- y taps ----
    float ty0 = fmaxf(y1 + ((float)ph + 0.25f) * bsh, 0.0f);
    float ty1 = fmaxf(y1 + ((float)ph + 0.75f) * bsh, 0.0f);
    int yl0 = min((int)ty0, HH - 1);
    int yl1 = min((int)ty1, HH - 1);
    int yh0 = min(yl0 + 1, HH - 1);
    int yh1 = min(yl1 + 1, HH - 1);
    float fy0 = (yl0 >= HH - 1) ? 0.0f : ty0 - (float)yl0;
    float fy1 = (yl1 >= HH - 1) ? 0.0f : ty1 - (float)yl1;

    float a0 = 1.0f - fy0, a1 = fy0;
    float a2 = 1.0f - fy1, a3 = fy1;

    // ---- branch-free row dedup (same load set as R4) ----
    bool same_pair = (yl1 == yl0);
    bool shift_one = (yl1 == yh0);
    bool act2 = !same_pair;
    bool act3 = !same_pair && !shift_one;
    int  row2 = shift_one ? yh1 : yl1;
    float wr0 = a0 + (same_pair ? a2 : 0.0f);
    float wr1 = a1 + (same_pair ? a3 : (shift_one ? a2 : 0.0f));
    float wr2 = shift_one ? a3 : a2;
    float wr3 = a3;

    // ---- aligned x window ----
    int wbase = xl0 & ~3;
    int o_l0 = xl0 - wbase, o_h0 = xh0 - wbase;
    int o_l1 = xl1 - wbase, o_h1 = xh1 - wbase;

    float acc;

    if (o_h1 <= 7) {
        float w[8];
        #pragma unroll
        for (int j = 0; j < 8; ++j) {
            float v = (j == o_l0) ? (1.0f - fx0) : 0.0f;
            v += (j == o_h0) ? fx0 : 0.0f;
            v += (j == o_l1) ? (1.0f - fx1) : 0.0f;
            v += (j == o_h1) ? fx1 : 0.0f;
            w[j] = v;
        }
        bool need2 = (o_h1 > 3);
        const float* rowbase = base + wbase;
        const float4* p0 = (const float4*)(rowbase + yl0 * WW);
        const float4* p1 = (const float4*)(rowbase + yh0 * WW);
        const float4* p2 = (const float4*)(rowbase + row2 * WW);
        const float4* p3 = (const float4*)(rowbase + yh1 * WW);

        // weighted vector accumulation over rows; single dot at the end
        float4 accA, accB;
        {
            float4 A0 = __ldg(p0);
            float4 A1 = __ldg(p1);
            accA.x = wr0 * A0.x + wr1 * A1.x;
            accA.y = wr0 * A0.y + wr1 * A1.y;
            accA.z = wr0 * A0.z + wr1 * A1.z;
            accA.w = wr0 * A0.w + wr1 * A1.w;
        }
        if (act2) {
            float4 A2 = __ldg(p2);
            accA.x += wr2 * A2.x; accA.y += wr2 * A2.y;
            accA.z += wr2 * A2.z; accA.w += wr2 * A2.w;
        }
        if (act3) {
            float4 A3 = __ldg(p3);
            accA.x += wr3 * A3.x; accA.y += wr3 * A3.y;
            accA.z += wr3 * A3.z; accA.w += wr3 * A3.w;
        }
        accB = make_float4(0.f, 0.f, 0.f, 0.f);
        if (need2) {
            float4 B0 = __ldg(p0 + 1);
            float4 B1 = __ldg(p1 + 1);
            accB.x = wr0 * B0.x + wr1 * B1.x;
            accB.y = wr0 * B0.y + wr1 * B1.y;
            accB.z = wr0 * B0.z + wr1 * B1.z;
            accB.w = wr0 * B0.w + wr1 * B1.w;
            if (act2) {
                float4 B2 = __ldg(p2 + 1);
                accB.x += wr2 * B2.x; accB.y += wr2 * B2.y;
                accB.z += wr2 * B2.z; accB.w += wr2 * B2.w;
            }
            if (act3) {
                float4 B3 = __ldg(p3 + 1);
                accB.x += wr3 * B3.x; accB.y += wr3 * B3.y;
                accB.z += wr3 * B3.z; accB.w += wr3 * B3.w;
            }
        }
        acc = accA.x * w[0] + accA.y * w[1] + accA.z * w[2] + accA.w * w[3]
            + accB.x * w[4] + accB.y * w[5] + accB.z * w[6] + accB.w * w[7];
    } else {
        // rare wide-roi fallback (block-uniform bsw -> usually warp-uniform skip)
        float wx0 = 1.0f - fx0, wx1 = fx0, wx2 = 1.0f - fx1, wx3 = fx1;
        const float* q0 = base + yl0 * WW;
        const float* q1 = base + yh0 * WW;
        float s0 = wx0 * __ldg(q0 + xl0) + wx1 * __ldg(q0 + xh0)
                 + wx2 * __ldg(q0 + xl1) + wx3 * __ldg(q0 + xh1);
        float s1 = wx0 * __ldg(q1 + xl0) + wx1 * __ldg(q1 + xh0)
                 + wx2 * __ldg(q1 + xl1) + wx3 * __ldg(q1 + xh1);
        float s2 = 0.f, s3 = 0.f;
        if (act2) {
            const float* q2 = base + row2 * WW;
            s2 = wx0 * __ldg(q2 + xl0) + wx1 * __ldg(q2 + xh0)
               + wx2 * __ldg(q2 + xl1) + wx3 * __ldg(q2 + xh1);
        }
        if (act3) {
            const float* q3 = base + yh1 * WW;
            s3 = wx0 * __ldg(q3 + xl0) + wx1 * __ldg(q3 + xh0)
               + wx2 * __ldg(q3 + xl1) + wx3 * __ldg(q3 + xh1);
        }
        acc = wr0 * s0 + wr1 * s1 + wr2 * s2 + wr3 * s3;
    }

    return acc * 0.25f;
}

__global__ __launch_bounds__(256, 4) void psroi_align_kernel(
    const float* __restrict__ input,
    const float* __restrict__ rois,
    float* __restrict__ out)
{
    int k = blockIdx.x;
    int t = threadIdx.x;

    const float* roi = rois + k * 5;
    int   b  = (int)__ldg(roi + 0);
    float x1 = __ldg(roi + 1) * SSCALE - 0.5f;
    float y1 = __ldg(roi + 2) * SSCALE - 0.5f;
    float x2 = __ldg(roi + 3) * SSCALE - 0.5f;
    float y2 = __ldg(roi + 4) * SSCALE - 0.5f;

    float bsh = (y2 - y1) * (1.0f / POOL);
    float bsw = (x2 - x1) * (1.0f / POOL);

    const float* baseimg = input + (long)b * C_TOT * PLANE;

    int r0 = t;                       // 0..255, always valid
    int r1 = min(t + 256, C_TOT - 1); // clamp; store predicated

    float v0 = compute_elem(baseimg, r0, x1, y1, bsw, bsh);
    float v1 = compute_elem(baseimg, r1, x1, y1, bsw, bsh);

    out[k * C_TOT + r0] = v0;
    if (t + 256 < C_TOT)
        out[k * C_TOT + t + 256] = v1;
}

extern "C" void kernel_launch(void* const* d_in, const int* in_sizes, int n_in,
                              void* d_out, int out_size)
{
    const float* input = (const float*)d_in[0];
    const float* rois  = (const float*)d_in[1];
    float* out = (float*)d_out;

    psroi_align_kernel<<<2048, 256>>>(input, rois, out);
}

// round 7
// speedup vs baseline: 1.1692x; 1.1603x over previous
#include <cuda_runtime.h>

// PS-ROI-Align, fixed dims:
//   input: (N=4, C=490, H=100, W=100) f32
//   rois:  (K=2048, 5) f32  [batch, x1, y1, x2, y2]
//   out:   (K, 10, 7, 7) f32,  POOL=7, SCALE=1/16, GRID=2
//
// One thread per output element, 2 blocks per roi (warp-uniform roi).
// Strategy: minimal predicated load set (rows 0,1 always; rows 2,3
// act-predicated; 2nd float4 per row need2-predicated) — same L1-wavefront
// count as the best kernel so far — but ALL loads are issued as one
// front batch (predicates/addresses computed first, math strictly after)
// so per-thread MLP ~= 8 and L2 latency is fully hidden.

#define C_TOT   490
#define HH      100
#define WW      100
#define POOL    7
#define SSCALE  0.0625f

__global__ __launch_bounds__(256) void psroi_align_kernel(
    const float* __restrict__ input,
    const float* __restrict__ rois,
    float* __restrict__ out)
{
    int k = blockIdx.x >> 1;
    int r = ((blockIdx.x & 1) << 8) + threadIdx.x;   // 0..511
    if (r >= C_TOT) return;

    int pw = r % POOL;
    int ph = (r / POOL) % POOL;

    const float* roi = rois + k * 5;
    int   b  = (int)__ldg(roi + 0);
    float x1 = __ldg(roi + 1) * SSCALE - 0.5f;
    float y1 = __ldg(roi + 2) * SSCALE - 0.5f;
    float x2 = __ldg(roi + 3) * SSCALE - 0.5f;
    float y2 = __ldg(roi + 4) * SSCALE - 0.5f;

    float bsh = (y2 - y1) * (1.0f / POOL);
    float bsw = (x2 - x1) * (1.0f / POOL);

    const float* base = input + ((long)b * C_TOT + r) * (HH * WW);

    // ---- x taps (samples at +0.25, +0.75 of bin) ----
    float tx0 = fmaxf(x1 + ((float)pw + 0.25f) * bsw, 0.0f);
    float tx1 = fmaxf(x1 + ((float)pw + 0.75f) * bsw, 0.0f);
    int xl0 = min((int)tx0, WW - 1);
    int xl1 = min((int)tx1, WW - 1);
    int xh0 = min(xl0 + 1, WW - 1);
    int xh1 = min(xl1 + 1, WW - 1);
    float fx0 = (xl0 >= WW - 1) ? 0.0f : tx0 - (float)xl0;
    float fx1 = (xl1 >= WW - 1) ? 0.0f : tx1 - (float)xl1;

    // ---- y taps ----
    float ty0 = fmaxf(y1 + ((float)ph + 0.25f) * bsh, 0.0f);
    float ty1 = fmaxf(y1 + ((float)ph + 0.75f) * bsh, 0.0f);
    int yl0 = min((int)ty0, HH - 1);
    int yl1 = min((int)ty1, HH - 1);
    int yh0 = min(yl0 + 1, HH - 1);
    int yh1 = min(yl1 + 1, HH - 1);
    float fy0 = (yl0 >= HH - 1) ? 0.0f : ty0 - (float)yl0;
    float fy1 = (yl1 >= HH - 1) ? 0.0f : ty1 - (float)yl1;

    float a0 = 1.0f - fy0, a1 = fy0;
    float a2 = 1.0f - fy1, a3 = fy1;

    // ---- branch-free row dedup ----
    bool same_pair = (yl1 == yl0);            // rows {2,3} duplicate {0,1}
    bool shift_one = (yl1 == yh0);            // row2 == row1
    bool act2 = !same_pair;
    bool act3 = !same_pair && !shift_one;
    int  row2 = shift_one ? yh1 : yl1;
    float wr0 = a0 + (same_pair ? a2 : 0.0f);
    float wr1 = a1 + (same_pair ? a3 : (shift_one ? a2 : 0.0f));
    float wr2 = shift_one ? a3 : a2;          // paired with zeroed A2/B2 when !act2
    float wr3 = a3;                           // paired with zeroed A3/B3 when !act3

    // ---- aligned x window ----
    int wbase = xl0 & ~3;                     // 16B aligned, in-bounds
    int o_l0 = xl0 - wbase, o_h0 = xh0 - wbase;
    int o_l1 = xl1 - wbase, o_h1 = xh1 - wbase;

    float acc;

    if (o_h1 <= 7) {
        bool need2 = (o_h1 > 3);
        const float* rowbase = base + wbase;
        const float4* p0 = (const float4*)(rowbase + yl0 * WW);
        const float4* p1 = (const float4*)(rowbase + yh0 * WW);
        const float4* p2 = (const float4*)(rowbase + row2 * WW);
        const float4* p3 = (const float4*)(rowbase + yh1 * WW);

        // ======== front-batched predicated loads, no math in between ========
        float4 Z  = make_float4(0.f, 0.f, 0.f, 0.f);
        float4 A0, A1, A2 = Z, A3 = Z, B0 = Z, B1 = Z, B2 = Z, B3 = Z;
        A0 = __ldg(p0);
        A1 = __ldg(p1);
        if (act2)          A2 = __ldg(p2);
        if (act3)          A3 = __ldg(p3);
        if (need2)         B0 = __ldg(p0 + 1);
        if (need2)         B1 = __ldg(p1 + 1);
        if (need2 && act2) B2 = __ldg(p2 + 1);
        if (need2 && act3) B3 = __ldg(p3 + 1);
        // ====================================================================

        // x-weight vector over the 8-float window
        float w[8];
        #pragma unroll
        for (int j = 0; j < 8; ++j) {
            float v = (j == o_l0) ? (1.0f - fx0) : 0.0f;
            v += (j == o_h0) ? fx0 : 0.0f;
            v += (j == o_l1) ? (1.0f - fx1) : 0.0f;
            v += (j == o_h1) ? fx1 : 0.0f;
            w[j] = v;
        }

        // weighted row accumulation (vector), then one dot with w[]
        float4 accA, accB;
        accA.x = wr0 * A0.x + wr1 * A1.x + wr2 * A2.x + wr3 * A3.x;
        accA.y = wr0 * A0.y + wr1 * A1.y + wr2 * A2.y + wr3 * A3.y;
        accA.z = wr0 * A0.z + wr1 * A1.z + wr2 * A2.z + wr3 * A3.z;
        accA.w = wr0 * A0.w + wr1 * A1.w + wr2 * A2.w + wr3 * A3.w;
        accB.x = wr0 * B0.x + wr1 * B1.x + wr2 * B2.x + wr3 * B3.x;
        accB.y = wr0 * B0.y + wr1 * B1.y + wr2 * B2.y + wr3 * B3.y;
        accB.z = wr0 * B0.z + wr1 * B1.z + wr2 * B2.z + wr3 * B3.z;
        accB.w = wr0 * B0.w + wr1 * B1.w + wr2 * B2.w + wr3 * B3.w;

        acc = accA.x * w[0] + accA.y * w[1] + accA.z * w[2] + accA.w * w[3]
            + accB.x * w[4] + accB.y * w[5] + accB.z * w[6] + accB.w * w[7];
    } else {
        // rare wide-roi fallback: scalar taps, same predication
        float wx0 = 1.0f - fx0, wx1 = fx0, wx2 = 1.0f - fx1, wx3 = fx1;
        const float* q0 = base + yl0 * WW;
        const float* q1 = base + yh0 * WW;
        const float* q2 = base + row2 * WW;
        const float* q3 = base + yh1 * WW;
        float s0 = wx0 * __ldg(q0 + xl0) + wx1 * __ldg(q0 + xh0)
                 + wx2 * __ldg(q0 + xl1) + wx3 * __ldg(q0 + xh1);
        float s1 = wx0 * __ldg(q1 + xl0) + wx1 * __ldg(q1 + xh0)
                 + wx2 * __ldg(q1 + xl1) + wx3 * __ldg(q1 + xh1);
        float s2 = 0.f, s3 = 0.f;
        if (act2)
            s2 = wx0 * __ldg(q2 + xl0) + wx1 * __ldg(q2 + xh0)
               + wx2 * __ldg(q2 + xl1) + wx3 * __ldg(q2 + xh1);
        if (act3)
            s3 = wx0 * __ldg(q3 + xl0) + wx1 * __ldg(q3 + xh0)
               + wx2 * __ldg(q3 + xl1) + wx3 * __ldg(q3 + xh1);
        acc = wr0 * s0 + wr1 * s1 + wr2 * s2 + wr3 * s3;
    }

    out[k * C_TOT + r] = acc * 0.25f;
}

extern "C" void kernel_launch(void* const* d_in, const int* in_sizes, int n_in,
                              void* d_out, int out_size)
{
    const float* input = (const float*)d_in[0];
    const float* rois  = (const float*)d_in[1];
    float* out = (float*)d_out;

    psroi_align_kernel<<<2048 * 2, 256>>>(input, rois, out);
}